// round 16
// baseline (speedup 1.0000x reference)
#include <cuda_runtime.h>
#include <math.h>

#define BATCH 512
#define DIM   65536
#define NWIN  13

// scratch: per batch b: slots 0..12 = raw quadratic forms, slot 13 = ||x||^2
__device__ float g_Q[BATCH * 16];
// coef[i*16+j] = (i==j ? A_ii : 2*A_ij) for j>=i else 0
__device__ float g_coef[256];
// per-b completion counter (2 CTAs per b)
__device__ int g_done[BATCH];

// ---------------------------------------------------------------------------
// Setup: build A = Re(U^H (X^{ox4}) U) in fp64. 1 block x 256 threads.
// ---------------------------------------------------------------------------
struct cplx { double re, im; };
__device__ __forceinline__ cplx cmul(cplx a, cplx b) {
    return { a.re*b.re - a.im*b.im, a.re*b.im + a.im*b.re };
}
__device__ __forceinline__ int ring_perm_inv(int k) {
    if (k & 1) k ^= 8;   // CNOT(3,0)
    if (k & 2) k ^= 1;   // CNOT(2,3)
    if (k & 4) k ^= 2;   // CNOT(1,2)
    if (k & 8) k ^= 4;   // CNOT(0,1)
    return k;
}

__global__ void setup_kernel(const float* __restrict__ w) {
    __shared__ cplx sA[256], sB[256], sY[256];
    __shared__ cplx ug[4][2][2];
    int tid = threadIdx.x;
    int r = tid >> 4, c = tid & 15;

    for (int layer = 0; layer < 3; ++layer) {
        if (tid < 4) {
            int q = tid, off = 12*layer + 3*q;
            double t0 = w[off], t1 = w[off+1], t2 = w[off+2];
            double c0 = cos(0.5*t0), s0 = sin(0.5*t0);
            double cz = cos(0.5*t1), sz = sin(0.5*t1);
            double c2 = cos(0.5*t2), s2 = sin(0.5*t2);
            cplx B00 = { cz*c0, -sz*c0 }, B01 = { -cz*s0, sz*s0 };
            cplx B10 = { cz*s0,  sz*s0 }, B11 = {  cz*c0, sz*c0 };
            ug[q][0][0] = { c2*B00.re - s2*B10.re, c2*B00.im - s2*B10.im };
            ug[q][0][1] = { c2*B01.re - s2*B11.re, c2*B01.im - s2*B11.im };
            ug[q][1][0] = { s2*B00.re + c2*B10.re, s2*B00.im + c2*B10.im };
            ug[q][1][1] = { s2*B01.re + c2*B11.re, s2*B01.im + c2*B11.im };
        }
        __syncthreads();

        cplx y = { 1.0, 0.0 };
        #pragma unroll
        for (int q = 0; q < 4; ++q)
            y = cmul(y, ug[q][(r >> (3-q)) & 1][(c >> (3-q)) & 1]);

        if (layer == 0) {
            sA[tid] = y;  __syncthreads();
        } else {
            sY[tid] = y;  __syncthreads();
            cplx acc = { 0.0, 0.0 };
            #pragma unroll
            for (int k = 0; k < 16; ++k) {
                cplx p = cmul(sY[r*16 + k], sA[k*16 + c]);
                acc.re += p.re; acc.im += p.im;
            }
            sB[tid] = acc; __syncthreads();
            sA[tid] = sB[tid]; __syncthreads();
        }
        if (layer < 2) {
            cplx v = sA[ring_perm_inv(r)*16 + c];
            __syncthreads();
            sA[tid] = v;
            __syncthreads();
        }
    }

    {
        int i = r, j = c;
        double are = 0.0;
        #pragma unroll
        for (int k = 0; k < 16; ++k) {
            cplx a = sA[k*16 + i], b = sA[(15-k)*16 + j];
            are += a.re*b.re + a.im*b.im;
        }
        g_coef[tid] = (j < i) ? 0.0f : (j == i ? (float)are : (float)(2.0*are));
    }
    for (int idx = tid; idx < BATCH*16; idx += 256) g_Q[idx] = 0.0f;
    for (int idx = tid; idx < BATCH;    idx += 256) g_done[idx] = 0;
}

// ---------------------------------------------------------------------------
// Helpers
// ---------------------------------------------------------------------------
__device__ __forceinline__ float warp_reduce(float v) {
    #pragma unroll
    for (int o = 16; o > 0; o >>= 1)
        v += __shfl_xor_sync(0xffffffffu, v, o);
    return v;
}

// Gram accumulate: first -> FMUL init (bit-exact vs fma into 0), else FMA.
__device__ __forceinline__ void gram_step(float* __restrict__ G,
                                          const float* __restrict__ xv,
                                          bool first) {
    int t = 0;
    if (first) {
        #pragma unroll
        for (int i = 0; i < 16; ++i)
            #pragma unroll
            for (int j = i; j < 16; ++j) { G[t] = xv[i] * xv[j]; ++t; }
    } else {
        #pragma unroll
        for (int i = 0; i < 16; ++i)
            #pragma unroll
            for (int j = i; j < 16; ++j) { G[t] = fmaf(xv[i], xv[j], G[t]); ++t; }
    }
}

__device__ __forceinline__ float contract(const float* __restrict__ G,
                                          const float* __restrict__ sC,
                                          bool want_tr, float& tr_out) {
    float a4[4] = {0.f,0.f,0.f,0.f};
    float tr = 0.f;
    int t = 0;
    #pragma unroll
    for (int i = 0; i < 16; ++i) {
        if (want_tr) tr += G[t];
        #pragma unroll
        for (int j = i; j < 16; ++j) {
            a4[t & 3] = fmaf(G[t], sC[i*16 + j], a4[t & 3]); ++t;
        }
    }
    tr_out = tr;
    return (a4[0]+a4[1]) + (a4[2]+a4[3]);
}

// ---------------------------------------------------------------------------
// Main: windows s=1..12 + s0 contribution + in-kernel finalize.
// Grid = BATCH*2 (one CTA per 128KB half-row), 256 threads, single-pass G[136].
//
// Swizzle f(L) = L ^ ((L>>4)&30) is XOR-linear over disjoint bit-fields.
// s=1..3 (lr=11,10,9): base decomposes into bit-disjoint (k, tid) fields with
//   f(k*256) = k*256 ^ 16*(k&1), and f(i<<lr) = i<<lr (no swizzle feed) ->
//   rb_k = (f(tid) ^ 16*(k&1)) + const(k);  load = LDS [rb_k + i*stride].
// s>=4 (lr<=8): stepping v += 256 steps base by exactly 4096 (lr-independent,
//   no swizzle feed) -> Ai[i] = f(base0) ^ f(i<<lr);  load = LDS [Ai + k*4096].
// launch_bounds(288) caps regs (~227) to stop ptxas over-prefetching (R14: 255).
// ---------------------------------------------------------------------------
__global__ void __launch_bounds__(288, 1)
gram_main_kernel(const float* __restrict__ x, float* __restrict__ out) {
    extern __shared__ float sm[];          // 32768 tile + 256 coef
    float* sC = sm + 32768;
    int tid = threadIdx.x;
    int b = blockIdx.x >> 1, tile = blockIdx.x & 1;
    const float* src = x + (size_t)b * DIM + tile * 32768;

    sC[tid] = g_coef[tid];

    #pragma unroll 4
    for (int it = 0; it < 32; ++it) {
        int f = it*256 + tid;
        float4 v = *(const float4*)(src + (f << 2));
        int L = f << 2, m = (L >> 4) & 30;
        *(float2*)(sm + (L ^ m))       = make_float2(v.x, v.y);
        *(float2*)(sm + ((L+2) ^ m))   = make_float2(v.z, v.w);
    }
    __syncthreads();

    const int ftid = tid ^ ((tid >> 4) & 30);

    // ---- window s = 1 (lr=11, stride 2048): rb + i*2048 imm ----
    {
        float G[136];
        #pragma unroll 2
        for (int k = 0; k < 8; ++k) {
            int rb = (ftid ^ (16 * (k & 1))) + k * 256;
            float xv[16];
            #pragma unroll
            for (int i = 0; i < 16; ++i) xv[i] = sm[rb + i * 2048];
            gram_step(G, xv, k == 0);
        }
        float tr;
        float acc = contract(G, sC, true, tr);
        acc = warp_reduce(acc);
        tr  = warp_reduce(tr);
        if ((tid & 31) == 0) {
            atomicAdd(&g_Q[b*16 + 1], acc);
            atomicAdd(&g_Q[b*16 + 13], tr);
        }
    }

    // ---- window s = 2 (lr=10, stride 1024): rb + i*1024 imm ----
    {
        float G[136];
        #pragma unroll 2
        for (int k = 0; k < 8; ++k) {
            int rb = (ftid ^ (16 * (k & 1))) + (k & 3) * 256 + (k >> 2) * 16384;
            float xv[16];
            #pragma unroll
            for (int i = 0; i < 16; ++i) xv[i] = sm[rb + i * 1024];
            gram_step(G, xv, k == 0);
        }
        float tr;
        float acc = contract(G, sC, false, tr);
        acc = warp_reduce(acc);
        if ((tid & 31) == 0) atomicAdd(&g_Q[b*16 + 2], acc);
    }

    // ---- window s = 3 (lr=9, stride 512): rb + i*512 imm ----
    {
        float G[136];
        #pragma unroll 2
        for (int k = 0; k < 8; ++k) {
            int rb = (ftid ^ (16 * (k & 1))) + (k & 1) * 256 + (k >> 1) * 8192;
            float xv[16];
            #pragma unroll
            for (int i = 0; i < 16; ++i) xv[i] = sm[rb + i * 512];
            gram_step(G, xv, k == 0);
        }
        float tr;
        float acc = contract(G, sC, false, tr);
        acc = warp_reduce(acc);
        if ((tid & 31) == 0) atomicAdd(&g_Q[b*16 + 3], acc);
    }

    // ---- windows s = 4..12 (lr <= 8): Ai + k*4096 imm, 2 groups of 4 ----
    #pragma unroll 1
    for (int s = 4; s <= 12; ++s) {
        const int lr = 12 - s;            // 8..0

        int a0 = tid >> lr;
        int base0 = (a0 << (lr + 4)) + (tid - (a0 << lr));
        int Pb0 = base0 ^ ((base0 >> 4) & 30);
        int Ai[16];
        #pragma unroll
        for (int i = 0; i < 16; ++i) {
            int sh = i << lr;
            Ai[i] = Pb0 ^ (sh ^ ((sh >> 4) & 30));
        }

        float G[136];
        #pragma unroll
        for (int k2 = 0; k2 < 2; ++k2) {
            #pragma unroll
            for (int k = 0; k < 4; ++k) {
                float xv[16];
                #pragma unroll
                for (int i = 0; i < 16; ++i)
                    xv[i] = sm[Ai[i] + k*4096];
                gram_step(G, xv, k2 == 0 && k == 0);
            }
            if (k2 == 0) {
                #pragma unroll
                for (int i = 0; i < 16; ++i) Ai[i] += 16384;
            }
        }

        float tr;
        float acc = contract(G, sC, false, tr);
        acc = warp_reduce(acc);
        if ((tid & 31) == 0) atomicAdd(&g_Q[b*16 + s], acc);
    }

    // ---- s0 contribution (stride 4096) ----
    // diag 8x8 block from own tile; i*4096 has bits >=12 only -> f(d+i*4096)=f(d)+i*4096
    float acc0;
    {
        float Gd[36];
        #pragma unroll 2
        for (int k = 0; k < 16; ++k) {
            int d = (k << 8) + tid;       // 0..4095
            int sd = d ^ ((d >> 4) & 30);
            float xv[8];
            #pragma unroll
            for (int i = 0; i < 8; ++i) xv[i] = sm[sd + i*4096];
            int t = 0;
            if (k == 0) {
                #pragma unroll
                for (int i = 0; i < 8; ++i)
                    #pragma unroll
                    for (int j = i; j < 8; ++j) { Gd[t] = xv[i] * xv[j]; ++t; }
            } else {
                #pragma unroll
                for (int i = 0; i < 8; ++i)
                    #pragma unroll
                    for (int j = i; j < 8; ++j) { Gd[t] = fmaf(xv[i], xv[j], Gd[t]); ++t; }
            }
        }
        int ofs = tile ? 8 : 0;           // tile0 -> rows 0..7, tile1 -> rows 8..15
        float a4[4] = {0.f,0.f,0.f,0.f};
        int t = 0;
        #pragma unroll
        for (int i = 0; i < 8; ++i)
            #pragma unroll
            for (int j = i; j < 8; ++j) {
                a4[t & 3] = fmaf(Gd[t], sC[(i+ofs)*16 + (j+ofs)], a4[t & 3]); ++t;
            }
        acc0 = (a4[0]+a4[1]) + (a4[2]+a4[3]);
    }

    // cross 8x8 block, d-range split between the two CTAs:
    //   tile0: d in [0,2048)    — rows i<8 from own smem, cols 8+j from global
    //   tile1: d in [2048,4096) — cols 8+j from own smem (local j*4096+d), rows from global
    {
        const float* base_g = x + (size_t)b * DIM;
        float Gc[64];
        #pragma unroll 2
        for (int k = 0; k < 8; ++k) {
            int d = (tile << 11) + (k << 8) + tid;
            int sd = d ^ ((d >> 4) & 30);
            float av[8], bv[8];
            if (tile == 0) {
                #pragma unroll
                for (int j = 0; j < 8; ++j) bv[j] = base_g[(8 + j)*4096 + d]; // coalesced LDG
                #pragma unroll
                for (int i = 0; i < 8; ++i) av[i] = sm[sd + i*4096];
            } else {
                #pragma unroll
                for (int i = 0; i < 8; ++i) av[i] = base_g[i*4096 + d];       // coalesced LDG
                // component 8+j at global (8+j)*4096 + d -> tile1-local j*4096 + d
                #pragma unroll
                for (int j = 0; j < 8; ++j) bv[j] = sm[sd + j*4096];
            }
            if (k == 0) {
                #pragma unroll
                for (int i = 0; i < 8; ++i)
                    #pragma unroll
                    for (int j = 0; j < 8; ++j)
                        Gc[i*8+j] = av[i] * bv[j];
            } else {
                #pragma unroll
                for (int i = 0; i < 8; ++i)
                    #pragma unroll
                    for (int j = 0; j < 8; ++j)
                        Gc[i*8+j] = fmaf(av[i], bv[j], Gc[i*8+j]);
            }
        }
        float a4[4] = {0.f,0.f,0.f,0.f};
        #pragma unroll
        for (int i = 0; i < 8; ++i)
            #pragma unroll
            for (int j = 0; j < 8; ++j)
                a4[j & 3] = fmaf(Gc[i*8+j], sC[i*16 + (8+j)], a4[j & 3]);
        acc0 += (a4[0]+a4[1]) + (a4[2]+a4[3]);
    }

    acc0 = warp_reduce(acc0);
    if ((tid & 31) == 0) atomicAdd(&g_Q[b*16 + 0], acc0);

    // ---- in-kernel finalize: second CTA of this b writes out[b][*] ----
    __shared__ int s_last;
    __syncthreads();
    if (tid == 0) {
        __threadfence();
        int old = atomicAdd(&g_done[b], 1);
        s_last = (old == 1);
    }
    __syncthreads();
    if (s_last) {
        __threadfence();
        if (tid < NWIN) {
            float q = atomicAdd(&g_Q[b*16 + tid], 0.0f);   // coherent read
            float n = atomicAdd(&g_Q[b*16 + 13],  0.0f);
            out[b*NWIN + tid] = q / n;
        }
    }
}

extern "C" void kernel_launch(void* const* d_in, const int* in_sizes, int n_in,
                              void* d_out, int out_size) {
    const float* x = (const float*)d_in[0];
    const float* w = (const float*)d_in[1];
    float* out = (float*)d_out;

    setup_kernel<<<1, 256>>>(w);

    size_t smem = (32768 + 256) * sizeof(float);
    cudaFuncSetAttribute(gram_main_kernel,
                         cudaFuncAttributeMaxDynamicSharedMemorySize, (int)smem);
    gram_main_kernel<<<BATCH * 2, 256, smem>>>(x, out);
}

// round 17
// speedup vs baseline: 1.7392x; 1.7392x over previous
#include <cuda_runtime.h>
#include <math.h>

#define BATCH 512
#define DIM   65536
#define NWIN  13

__device__ float g_Q[BATCH * 16];
__device__ float g_coef[256];
__device__ int g_done[BATCH];

// ---------------------------------------------------------------------------
// Setup: build A = Re(U^H (X^{ox4}) U) in fp64. 1 block x 256 threads.
// ---------------------------------------------------------------------------
struct cplx { double re, im; };
__device__ __forceinline__ cplx cmul(cplx a, cplx b) {
    return { a.re*b.re - a.im*b.im, a.re*b.im + a.im*b.re };
}
__device__ __forceinline__ int ring_perm_inv(int k) {
    if (k & 1) k ^= 8;   // CNOT(3,0)
    if (k & 2) k ^= 1;   // CNOT(2,3)
    if (k & 4) k ^= 2;   // CNOT(1,2)
    if (k & 8) k ^= 4;   // CNOT(0,1)
    return k;
}

__global__ void setup_kernel(const float* __restrict__ w) {
    __shared__ cplx sA[256], sB[256], sY[256];
    __shared__ cplx ug[4][2][2];
    int tid = threadIdx.x;
    int r = tid >> 4, c = tid & 15;

    for (int layer = 0; layer < 3; ++layer) {
        if (tid < 4) {
            int q = tid, off = 12*layer + 3*q;
            double t0 = w[off], t1 = w[off+1], t2 = w[off+2];
            double c0 = cos(0.5*t0), s0 = sin(0.5*t0);
            double cz = cos(0.5*t1), sz = sin(0.5*t1);
            double c2 = cos(0.5*t2), s2 = sin(0.5*t2);
            cplx B00 = { cz*c0, -sz*c0 }, B01 = { -cz*s0, sz*s0 };
            cplx B10 = { cz*s0,  sz*s0 }, B11 = {  cz*c0, sz*c0 };
            ug[q][0][0] = { c2*B00.re - s2*B10.re, c2*B00.im - s2*B10.im };
            ug[q][0][1] = { c2*B01.re - s2*B11.re, c2*B01.im - s2*B11.im };
            ug[q][1][0] = { s2*B00.re + c2*B10.re, s2*B00.im + c2*B10.im };
            ug[q][1][1] = { s2*B01.re + c2*B11.re, s2*B01.im + c2*B11.im };
        }
        __syncthreads();

        cplx y = { 1.0, 0.0 };
        #pragma unroll
        for (int q = 0; q < 4; ++q)
            y = cmul(y, ug[q][(r >> (3-q)) & 1][(c >> (3-q)) & 1]);

        if (layer == 0) {
            sA[tid] = y;  __syncthreads();
        } else {
            sY[tid] = y;  __syncthreads();
            cplx acc = { 0.0, 0.0 };
            #pragma unroll
            for (int k = 0; k < 16; ++k) {
                cplx p = cmul(sY[r*16 + k], sA[k*16 + c]);
                acc.re += p.re; acc.im += p.im;
            }
            sB[tid] = acc; __syncthreads();
            sA[tid] = sB[tid]; __syncthreads();
        }
        if (layer < 2) {
            cplx v = sA[ring_perm_inv(r)*16 + c];
            __syncthreads();
            sA[tid] = v;
            __syncthreads();
        }
    }

    {
        int i = r, j = c;
        double are = 0.0;
        #pragma unroll
        for (int k = 0; k < 16; ++k) {
            cplx a = sA[k*16 + i], b = sA[(15-k)*16 + j];
            are += a.re*b.re + a.im*b.im;
        }
        g_coef[tid] = (j < i) ? 0.0f : (j == i ? (float)are : (float)(2.0*are));
    }
    for (int idx = tid; idx < BATCH*16; idx += 256) g_Q[idx] = 0.0f;
    for (int idx = tid; idx < BATCH;    idx += 256) g_done[idx] = 0;
}

// ---------------------------------------------------------------------------
// Helpers
// ---------------------------------------------------------------------------
__device__ __forceinline__ float warp_reduce(float v) {
    #pragma unroll
    for (int o = 16; o > 0; o >>= 1)
        v += __shfl_xor_sync(0xffffffffu, v, o);
    return v;
}

// Gram accumulate: first -> FMUL init (bit-exact vs fma into 0), else FMA.
__device__ __forceinline__ void gram_step(float* __restrict__ G,
                                          const float* __restrict__ xv,
                                          bool first) {
    int t = 0;
    if (first) {
        #pragma unroll
        for (int i = 0; i < 16; ++i)
            #pragma unroll
            for (int j = i; j < 16; ++j) { G[t] = xv[i] * xv[j]; ++t; }
    } else {
        #pragma unroll
        for (int i = 0; i < 16; ++i)
            #pragma unroll
            for (int j = i; j < 16; ++j) { G[t] = fmaf(xv[i], xv[j], G[t]); ++t; }
    }
}

__device__ __forceinline__ float contract(const float* __restrict__ G,
                                          const float* __restrict__ sC,
                                          bool want_tr, float& tr_out) {
    float a4[4] = {0.f,0.f,0.f,0.f};
    float tr = 0.f;
    int t = 0;
    #pragma unroll
    for (int i = 0; i < 16; ++i) {
        if (want_tr) tr += G[t];
        #pragma unroll
        for (int j = i; j < 16; ++j) {
            a4[t & 3] = fmaf(G[t], sC[i*16 + j], a4[t & 3]); ++t;
        }
    }
    tr_out = tr;
    return (a4[0]+a4[1]) + (a4[2]+a4[3]);
}

// ---------------------------------------------------------------------------
// Main: windows s=1..12 + s0 contribution + in-kernel finalize.
// Grid = BATCH*2 (one CTA per 128KB half-row), 256 threads, single-pass G[136].
// Swizzle f(L) = L ^ ((L>>4)&30), XOR-linear over disjoint bit-fields:
//  s=1..3: rb_k = (f(tid) ^ 16*(k&1)) + const(k); load = LDS [rb_k + i*stride]
//  s>=4:   Ai[i] = f(base0) ^ f(i<<lr); load = LDS [Ai + {0,4096}], Ai += 8192
// launch_bounds(256,1): 255-reg ceiling, no spills at ~190 live (R15 lesson).
// ---------------------------------------------------------------------------
__global__ void __launch_bounds__(256, 1)
gram_main_kernel(const float* __restrict__ x, float* __restrict__ out) {
    extern __shared__ float sm[];          // 32768 tile + 256 coef
    float* sC = sm + 32768;
    int tid = threadIdx.x;
    int b = blockIdx.x >> 1, tile = blockIdx.x & 1;
    const float* src = x + (size_t)b * DIM + tile * 32768;

    sC[tid] = g_coef[tid];

    #pragma unroll 4
    for (int it = 0; it < 32; ++it) {
        int f = it*256 + tid;
        float4 v = *(const float4*)(src + (f << 2));
        int L = f << 2, m = (L >> 4) & 30;
        *(float2*)(sm + (L ^ m))       = make_float2(v.x, v.y);
        *(float2*)(sm + ((L+2) ^ m))   = make_float2(v.z, v.w);
    }
    __syncthreads();

    const int ftid = tid ^ ((tid >> 4) & 30);

    // ---- window s = 1 (stride 2048) ----
    {
        float G[136];
        #pragma unroll 2
        for (int k = 0; k < 8; ++k) {
            int rb = (ftid ^ (16 * (k & 1))) + k * 256;
            float xv[16];
            #pragma unroll
            for (int i = 0; i < 16; ++i) xv[i] = sm[rb + i * 2048];
            gram_step(G, xv, k == 0);
        }
        float tr;
        float acc = contract(G, sC, true, tr);
        acc = warp_reduce(acc);
        tr  = warp_reduce(tr);
        if ((tid & 31) == 0) {
            atomicAdd(&g_Q[b*16 + 1], acc);
            atomicAdd(&g_Q[b*16 + 13], tr);
        }
    }

    // ---- window s = 2 (stride 1024) ----
    {
        float G[136];
        #pragma unroll 2
        for (int k = 0; k < 8; ++k) {
            int rb = (ftid ^ (16 * (k & 1))) + (k & 3) * 256 + (k >> 2) * 16384;
            float xv[16];
            #pragma unroll
            for (int i = 0; i < 16; ++i) xv[i] = sm[rb + i * 1024];
            gram_step(G, xv, k == 0);
        }
        float tr;
        float acc = contract(G, sC, false, tr);
        acc = warp_reduce(acc);
        if ((tid & 31) == 0) atomicAdd(&g_Q[b*16 + 2], acc);
    }

    // ---- window s = 3 (stride 512) ----
    {
        float G[136];
        #pragma unroll 2
        for (int k = 0; k < 8; ++k) {
            int rb = (ftid ^ (16 * (k & 1))) + (k & 1) * 256 + (k >> 1) * 8192;
            float xv[16];
            #pragma unroll
            for (int i = 0; i < 16; ++i) xv[i] = sm[rb + i * 512];
            gram_step(G, xv, k == 0);
        }
        float tr;
        float acc = contract(G, sC, false, tr);
        acc = warp_reduce(acc);
        if ((tid & 31) == 0) atomicAdd(&g_Q[b*16 + 3], acc);
    }

    // ---- windows s = 4..12 (lr <= 8): Ai + imm{0,4096}, bump 8192/iter ----
    #pragma unroll 1
    for (int s = 4; s <= 12; ++s) {
        const int lr = 12 - s;            // 8..0

        int a0 = tid >> lr;
        int base0 = (a0 << (lr + 4)) + (tid - (a0 << lr));
        int Pb0 = base0 ^ ((base0 >> 4) & 30);
        int Ai[16];
        #pragma unroll
        for (int i = 0; i < 16; ++i) {
            int sh = i << lr;
            Ai[i] = Pb0 ^ (sh ^ ((sh >> 4) & 30));
        }

        float G[136];
        // peel pair k = {0,1}: FMUL init
        {
            float xv[16];
            #pragma unroll
            for (int i = 0; i < 16; ++i) xv[i] = sm[Ai[i]];
            gram_step(G, xv, true);
            #pragma unroll
            for (int i = 0; i < 16; ++i) xv[i] = sm[Ai[i] + 4096];
            gram_step(G, xv, false);
        }
        #pragma unroll 1
        for (int k2 = 1; k2 < 4; ++k2) {  // pairs {2,3},{4,5},{6,7}
            #pragma unroll
            for (int i = 0; i < 16; ++i) Ai[i] += 8192;
            float xv[16];
            #pragma unroll
            for (int i = 0; i < 16; ++i) xv[i] = sm[Ai[i]];
            gram_step(G, xv, false);
            #pragma unroll
            for (int i = 0; i < 16; ++i) xv[i] = sm[Ai[i] + 4096];
            gram_step(G, xv, false);
        }

        float tr;
        float acc = contract(G, sC, false, tr);
        acc = warp_reduce(acc);
        if ((tid & 31) == 0) atomicAdd(&g_Q[b*16 + s], acc);
    }

    // ---- s0 contribution (stride 4096) ----
    float acc0;
    {
        float Gd[36];
        #pragma unroll 2
        for (int k = 0; k < 16; ++k) {
            int d = (k << 8) + tid;       // 0..4095
            int sd = d ^ ((d >> 4) & 30);
            float xv[8];
            #pragma unroll
            for (int i = 0; i < 8; ++i) xv[i] = sm[sd + i*4096];
            int t = 0;
            if (k == 0) {
                #pragma unroll
                for (int i = 0; i < 8; ++i)
                    #pragma unroll
                    for (int j = i; j < 8; ++j) { Gd[t] = xv[i] * xv[j]; ++t; }
            } else {
                #pragma unroll
                for (int i = 0; i < 8; ++i)
                    #pragma unroll
                    for (int j = i; j < 8; ++j) { Gd[t] = fmaf(xv[i], xv[j], Gd[t]); ++t; }
            }
        }
        int ofs = tile ? 8 : 0;
        float a4[4] = {0.f,0.f,0.f,0.f};
        int t = 0;
        #pragma unroll
        for (int i = 0; i < 8; ++i)
            #pragma unroll
            for (int j = i; j < 8; ++j) {
                a4[t & 3] = fmaf(Gd[t], sC[(i+ofs)*16 + (j+ofs)], a4[t & 3]); ++t;
            }
        acc0 = (a4[0]+a4[1]) + (a4[2]+a4[3]);
    }

    // cross 8x8 block, d-range split between the two CTAs
    {
        const float* base_g = x + (size_t)b * DIM;
        float Gc[64];
        #pragma unroll 2
        for (int k = 0; k < 8; ++k) {
            int d = (tile << 11) + (k << 8) + tid;
            int sd = d ^ ((d >> 4) & 30);
            float av[8], bv[8];
            if (tile == 0) {
                #pragma unroll
                for (int j = 0; j < 8; ++j) bv[j] = base_g[(8 + j)*4096 + d];
                #pragma unroll
                for (int i = 0; i < 8; ++i) av[i] = sm[sd + i*4096];
            } else {
                #pragma unroll
                for (int i = 0; i < 8; ++i) av[i] = base_g[i*4096 + d];
                #pragma unroll
                for (int j = 0; j < 8; ++j) bv[j] = sm[sd + j*4096];
            }
            if (k == 0) {
                #pragma unroll
                for (int i = 0; i < 8; ++i)
                    #pragma unroll
                    for (int j = 0; j < 8; ++j)
                        Gc[i*8+j] = av[i] * bv[j];
            } else {
                #pragma unroll
                for (int i = 0; i < 8; ++i)
                    #pragma unroll
                    for (int j = 0; j < 8; ++j)
                        Gc[i*8+j] = fmaf(av[i], bv[j], Gc[i*8+j]);
            }
        }
        float a4[4] = {0.f,0.f,0.f,0.f};
        #pragma unroll
        for (int i = 0; i < 8; ++i)
            #pragma unroll
            for (int j = 0; j < 8; ++j)
                a4[j & 3] = fmaf(Gc[i*8+j], sC[i*16 + (8+j)], a4[j & 3]);
        acc0 += (a4[0]+a4[1]) + (a4[2]+a4[3]);
    }

    acc0 = warp_reduce(acc0);
    if ((tid & 31) == 0) atomicAdd(&g_Q[b*16 + 0], acc0);

    // ---- in-kernel finalize ----
    __shared__ int s_last;
    __syncthreads();
    if (tid == 0) {
        __threadfence();
        int old = atomicAdd(&g_done[b], 1);
        s_last = (old == 1);
    }
    __syncthreads();
    if (s_last) {
        __threadfence();
        if (tid < NWIN) {
            float q = atomicAdd(&g_Q[b*16 + tid], 0.0f);
            float n = atomicAdd(&g_Q[b*16 + 13],  0.0f);
            out[b*NWIN + tid] = q / n;
        }
    }
}

extern "C" void kernel_launch(void* const* d_in, const int* in_sizes, int n_in,
                              void* d_out, int out_size) {
    const float* x = (const float*)d_in[0];
    const float* w = (const float*)d_in[1];
    float* out = (float*)d_out;

    setup_kernel<<<1, 256>>>(w);

    size_t smem = (32768 + 256) * sizeof(float);
    cudaFuncSetAttribute(gram_main_kernel,
                         cudaFuncAttributeMaxDynamicSharedMemorySize, (int)smem);
    gram_main_kernel<<<BATCH * 2, 256, smem>>>(x, out);
}